// round 2
// baseline (speedup 1.0000x reference)
#include <cuda_runtime.h>

// Problem constants
#define BATCH 32
#define DIM   256
#define HGT   32
#define WID   32
#define HW    1024            // H*W
#define NPTS  32768           // B*H*W
#define KCODE 1024
#define ZQ_ELEMS 8388608      // NPTS*DIM
#define IDX_OFF  ZQ_ELEMS
#define LOSS_OFF (ZQ_ELEMS + NPTS)

// Scratch (device globals — no allocation allowed in kernel_launch)
__device__ float  g_zt[NPTS * DIM];   // z transposed to [N, D], 32MB
__device__ int    g_idx[NPTS];
__device__ float  g_normE[KCODE];     // t2 = ||e_k||^2
__device__ float  g_t1[NPTS];         // t1 = ||z_n||^2 (sequential-order emulation)
__device__ double g_loss;

// ---------- f32x2 packed helpers ----------
__device__ __forceinline__ unsigned long long pack2(float x, float y) {
    unsigned long long r;
    asm("mov.b64 %0, {%1, %2};" : "=l"(r) : "f"(x), "f"(y));
    return r;
}
__device__ __forceinline__ void unpack2(unsigned long long p, float& x, float& y) {
    asm("mov.b64 {%0, %1}, %2;" : "=f"(x), "=f"(y) : "l"(p));
}
__device__ __forceinline__ void fma2(unsigned long long& d, unsigned long long a, unsigned long long b) {
    asm("fma.rn.f32x2 %0, %1, %2, %0;" : "+l"(d) : "l"(a), "l"(b));
}

// ---------- Kernel 1: codebook norms + loss reset ----------
__global__ void norms_k(const float* __restrict__ cb) {
    int k = blockIdx.x;
    float x = cb[k * DIM + threadIdx.x];
    float v = __fmul_rn(x, x);
    __shared__ float s[8];
    #pragma unroll
    for (int o = 16; o; o >>= 1) v += __shfl_down_sync(0xffffffffu, v, o);
    if ((threadIdx.x & 31) == 0) s[threadIdx.x >> 5] = v;
    __syncthreads();
    if (threadIdx.x < 8) {
        float t = s[threadIdx.x];
        #pragma unroll
        for (int o = 4; o; o >>= 1) t += __shfl_down_sync(0xffu, t, o);
        if (threadIdx.x == 0) {
            g_normE[k] = t;
            if (blockIdx.x == 0) g_loss = 0.0;
        }
    }
}

// ---------- Kernel 2: transpose z [B,D,H,W] -> zt [N,D] ----------
__global__ void transpose_k(const float* __restrict__ z) {
    __shared__ float tile[32][33];
    int b  = blockIdx.z;
    int p0 = blockIdx.x * 32;   // position within HW
    int d0 = blockIdx.y * 32;   // channel
    const float* src = z + (size_t)b * DIM * HW;
    #pragma unroll
    for (int i = 0; i < 32; i += 8)
        tile[threadIdx.y + i][threadIdx.x] = src[(d0 + threadIdx.y + i) * HW + p0 + threadIdx.x];
    __syncthreads();
    #pragma unroll
    for (int i = 0; i < 32; i += 8)
        g_zt[(b * HW + p0 + threadIdx.y + i) * DIM + d0 + threadIdx.x] = tile[threadIdx.x][threadIdx.y + i];
}

// ---------- Kernel 2b: row norms t1 = sum_d fl(z_d^2), STRICT sequential order ----------
// Emulates XLA's in-order minor-dim reduction (the one term whose rounding,
// at scale ~256, decides the reference's quantized-distance tie outcomes).
__global__ __launch_bounds__(256) void rownorm_k() {
    __shared__ float srow[32 * 257];   // pad to kill LDS bank conflicts
    int base = blockIdx.x * 32;        // 32 rows per block
    // coalesced load of 32 rows
    for (int idx = threadIdx.x; idx < 32 * 256; idx += 256) {
        int r = idx >> 8, c = idx & 255;
        srow[r * 257 + c] = g_zt[(base + r) * DIM + c];
    }
    __syncthreads();
    if (threadIdx.x < 32) {
        const float* row = &srow[threadIdx.x * 257];
        float acc = 0.0f;
        #pragma unroll 8
        for (int d = 0; d < 256; d++)
            acc = __fadd_rn(acc, __fmul_rn(row[d], row[d]));
        g_t1[base + threadIdx.x] = acc;
    }
}

// ---------- Kernel 3: fused GEMM + argmin (reference-formula emulation) ----------
// t3 = zt @ cb^T (fp32, any order: insensitive at ~1e-10);
// dist = fl(fl(t1 + t2_k) - 2*t3_k); argmin with first-index tie-break.
__global__ __launch_bounds__(256) void gemm_argmin_k(const float* __restrict__ cb) {
    __shared__ float zs[16][128];
    __shared__ float cs[16][128];
    __shared__ float rv[128][16];
    __shared__ int   ri[128][16];

    const int tid = threadIdx.x;
    const int tx = tid & 15;      // code sub-tile
    const int ty = tid >> 4;      // row sub-tile
    const int m0 = blockIdx.x * 128;
    const int lr = tid >> 2;          // load row 0..63
    const int lc = (tid & 3) * 4;     // load col {0,4,8,12}

    float bestV[8];
    int   bestI[8];
    float t1r[8];
    #pragma unroll
    for (int i = 0; i < 8; i++) {
        bestV[i] = 3.4e38f; bestI[i] = 0;
        t1r[i] = g_t1[m0 + ty * 8 + i];
    }

    for (int k0 = 0; k0 < KCODE; k0 += 128) {
        unsigned long long acc[8][4];
        #pragma unroll
        for (int i = 0; i < 8; i++)
            #pragma unroll
            for (int j = 0; j < 4; j++) acc[i][j] = 0ull;   // packed (0.f,0.f)

        for (int d0 = 0; d0 < DIM; d0 += 16) {
            float4 va0 = *(const float4*)&g_zt[(m0 + lr)      * DIM + d0 + lc];
            float4 va1 = *(const float4*)&g_zt[(m0 + lr + 64) * DIM + d0 + lc];
            float4 vb0 = *(const float4*)&cb [(k0 + lr)      * DIM + d0 + lc];
            float4 vb1 = *(const float4*)&cb [(k0 + lr + 64) * DIM + d0 + lc];
            __syncthreads();   // previous-iter readers done before overwrite
            zs[lc + 0][lr] = va0.x; zs[lc + 1][lr] = va0.y; zs[lc + 2][lr] = va0.z; zs[lc + 3][lr] = va0.w;
            zs[lc + 0][lr + 64] = va1.x; zs[lc + 1][lr + 64] = va1.y; zs[lc + 2][lr + 64] = va1.z; zs[lc + 3][lr + 64] = va1.w;
            cs[lc + 0][lr] = vb0.x; cs[lc + 1][lr] = vb0.y; cs[lc + 2][lr] = vb0.z; cs[lc + 3][lr] = vb0.w;
            cs[lc + 0][lr + 64] = vb1.x; cs[lc + 1][lr + 64] = vb1.y; cs[lc + 2][lr + 64] = vb1.z; cs[lc + 3][lr + 64] = vb1.w;
            __syncthreads();

            #pragma unroll
            for (int dd = 0; dd < 16; dd++) {
                float4 a0 = *(const float4*)&zs[dd][ty * 8];
                float4 a1 = *(const float4*)&zs[dd][ty * 8 + 4];
                ulonglong2 b0 = *(const ulonglong2*)&cs[dd][tx * 8];
                ulonglong2 b1 = *(const ulonglong2*)&cs[dd][tx * 8 + 4];
                unsigned long long bb[4] = { b0.x, b0.y, b1.x, b1.y };
                unsigned long long aa[8];
                aa[0] = pack2(a0.x, a0.x); aa[1] = pack2(a0.y, a0.y);
                aa[2] = pack2(a0.z, a0.z); aa[3] = pack2(a0.w, a0.w);
                aa[4] = pack2(a1.x, a1.x); aa[5] = pack2(a1.y, a1.y);
                aa[6] = pack2(a1.z, a1.z); aa[7] = pack2(a1.w, a1.w);
                #pragma unroll
                for (int i = 0; i < 8; i++)
                    #pragma unroll
                    for (int j = 0; j < 4; j++)
                        fma2(acc[i][j], aa[i], bb[j]);
            }
        }

        // epilogue: dist = fl(fl(t1 + t2_k) - 2*t3_k), running first-min argmin
        float ne[8];
        #pragma unroll
        for (int j = 0; j < 8; j++) ne[j] = g_normE[k0 + tx * 8 + j];
        #pragma unroll
        for (int i = 0; i < 8; i++) {
            #pragma unroll
            for (int j = 0; j < 4; j++) {
                float s0, s1;
                unpack2(acc[i][j], s0, s1);
                float dA = __fsub_rn(__fadd_rn(t1r[i], ne[2 * j]),     __fmul_rn(2.0f, s0));
                float dB = __fsub_rn(__fadd_rn(t1r[i], ne[2 * j + 1]), __fmul_rn(2.0f, s1));
                int kA = k0 + tx * 8 + 2 * j;
                if (dA < bestV[i]) { bestV[i] = dA; bestI[i] = kA; }      // strict <: first
                if (dB < bestV[i]) { bestV[i] = dB; bestI[i] = kA + 1; }  // index wins ties
            }
        }
    }

    // reduce across the 16 tx-threads that share each row (lowest index on ties)
    #pragma unroll
    for (int i = 0; i < 8; i++) { rv[ty * 8 + i][tx] = bestV[i]; ri[ty * 8 + i][tx] = bestI[i]; }
    __syncthreads();
    if (tid < 128) {
        float bv = rv[tid][0]; int bi = ri[tid][0];
        #pragma unroll
        for (int t = 1; t < 16; t++) {
            float v = rv[tid][t]; int ii = ri[tid][t];
            if (v < bv || (v == bv && ii < bi)) { bv = v; bi = ii; }
        }
        g_idx[m0 + tid] = bi;
    }
}

// ---------- Kernel 4: straight-through z_q + loss partial ----------
// out = fl(z + fl(q - z)) exactly mimics zt + sg(z_q - zt) elementwise.
__global__ void gather_loss_k(const float* __restrict__ z, const float* __restrict__ cb,
                              float* __restrict__ out) {
    int i = blockIdx.x * 256 + threadIdx.x;      // index into [B,D,H,W] flat
    int p = i & (HW - 1);
    int d = (i >> 10) & (DIM - 1);
    int b = i >> 18;
    int n = (b << 10) | p;
    float zv = z[i];
    float q  = cb[g_idx[n] * DIM + d];
    float diff = __fsub_rn(q, zv);
    out[i] = __fadd_rn(zv, diff);
    float sq = __fmul_rn(diff, diff);

    __shared__ float s[8];
    float v = sq;
    #pragma unroll
    for (int o = 16; o; o >>= 1) v += __shfl_down_sync(0xffffffffu, v, o);
    if ((threadIdx.x & 31) == 0) s[threadIdx.x >> 5] = v;
    __syncthreads();
    if (threadIdx.x < 8) {
        float t = s[threadIdx.x];
        #pragma unroll
        for (int o = 4; o; o >>= 1) t += __shfl_down_sync(0xffu, t, o);
        if (threadIdx.x == 0) atomicAdd(&g_loss, (double)t);
    }
}

// ---------- Kernel 5: idx (as float) + loss finalize ----------
__global__ void finalize_k(float* __restrict__ out, int write_loss) {
    int t = blockIdx.x * 256 + threadIdx.x;
    if (t < NPTS) out[IDX_OFF + t] = (float)g_idx[t];
    if (t == 0 && write_loss)
        out[LOSS_OFF] = (float)(1.25 * g_loss / (double)ZQ_ELEMS);
}

extern "C" void kernel_launch(void* const* d_in, const int* in_sizes, int n_in,
                              void* d_out, int out_size) {
    const float* z  = (const float*)d_in[0];   // [32,256,32,32] f32
    const float* cb = (const float*)d_in[1];   // [1024,256] f32
    float* out = (float*)d_out;

    norms_k<<<KCODE, 256>>>(cb);
    transpose_k<<<dim3(HW / 32, DIM / 32, BATCH), dim3(32, 8)>>>(z);
    rownorm_k<<<NPTS / 32, 256>>>();
    gemm_argmin_k<<<NPTS / 128, 256>>>(cb);
    gather_loss_k<<<ZQ_ELEMS / 256, 256>>>(z, cb, out);

    int write_idx  = (out_size >= IDX_OFF + NPTS);
    int write_loss = (out_size >= LOSS_OFF + 1);
    if (write_idx) finalize_k<<<NPTS / 256, 256>>>(out, write_loss);
}

// round 4
// speedup vs baseline: 1.6675x; 1.6675x over previous
#include <cuda_runtime.h>
#include <cuda_bf16.h>
#include <cstdint>

// Problem constants
#define BATCH 32
#define DIM   256
#define HW    1024
#define NPTS  32768
#define KCODE 1024
#define ZQ_ELEMS 8388608
#define IDX_OFF  ZQ_ELEMS
#define LOSS_OFF (ZQ_ELEMS + NPTS)

#define NSLOT 3           // top-3 per (thread,row) slot
#define NCROW 48          // 16 slots * 3 candidates per row
#define MARGIN 7e-4f

// Scratch (device globals)
__device__ float          g_zt [NPTS * DIM];     // z^T fp32 [N,D]
__device__ __nv_bfloat16  g_zth[NPTS * DIM];     // z^T bf16
__device__ __nv_bfloat16  g_cbh[KCODE * DIM];    // codebook bf16
__device__ int            g_idx[NPTS];
__device__ float          g_normE[KCODE];        // t2
__device__ float          g_t1[NPTS];            // t1 (sequential emulation)
__device__ float          g_candV[NPTS * NCROW];
__device__ int            g_candI[NPTS * NCROW];
__device__ double         g_loss;

// ================= generic PTX helpers (NO sm_103a-only instructions) ===========
__device__ __forceinline__ uint32_t smem_u32(const void* p) {
    uint32_t a;
    asm("{ .reg .u64 t; cvta.to.shared.u64 t, %1; cvt.u32.u64 %0, t; }" : "=r"(a) : "l"(p));
    return a;
}
#define CP_ASYNC16(dst, src) \
    asm volatile("cp.async.cg.shared.global [%0], [%1], 16;" :: "r"(dst), "l"(src) : "memory")
#define CP_COMMIT() asm volatile("cp.async.commit_group;" ::: "memory")
#define CP_WAIT0()  asm volatile("cp.async.wait_group 0;" ::: "memory")
#define CP_WAIT1()  asm volatile("cp.async.wait_group 1;" ::: "memory")

#define LDSM4(r0, r1, r2, r3, addr) \
    asm volatile("ldmatrix.sync.aligned.m8n8.x4.shared.b16 {%0,%1,%2,%3}, [%4];" \
        : "=r"(r0), "=r"(r1), "=r"(r2), "=r"(r3) : "r"(addr))

#define MMA16816(C, A, b0, b1) \
    asm volatile("mma.sync.aligned.m16n8k16.row.col.f32.bf16.bf16.f32 " \
        "{%0,%1,%2,%3},{%4,%5,%6,%7},{%8,%9},{%0,%1,%2,%3};" \
        : "+f"((C)[0]), "+f"((C)[1]), "+f"((C)[2]), "+f"((C)[3]) \
        : "r"((A)[0]), "r"((A)[1]), "r"((A)[2]), "r"((A)[3]), "r"(b0), "r"(b1))

// swizzled smem offset for bf16 tile [128 rows][256 cols], 512B/row, 16B chunks
__device__ __forceinline__ uint32_t sw_off(int row, int c16) {
    return (uint32_t)(row * 512 + ((c16 ^ (row & 7)) << 4));
}

// ================= Kernel 1: codebook norms + bf16 cvt + loss reset =============
__global__ void norms_k(const float* __restrict__ cb) {
    int k = blockIdx.x;
    float x = cb[k * DIM + threadIdx.x];
    g_cbh[k * DIM + threadIdx.x] = __float2bfloat16(x);
    float v = __fmul_rn(x, x);
    __shared__ float s[8];
    #pragma unroll
    for (int o = 16; o; o >>= 1) v += __shfl_down_sync(0xffffffffu, v, o);
    if ((threadIdx.x & 31) == 0) s[threadIdx.x >> 5] = v;
    __syncthreads();
    if (threadIdx.x < 8) {
        float t = s[threadIdx.x];
        #pragma unroll
        for (int o = 4; o; o >>= 1) t += __shfl_down_sync(0xffu, t, o);
        if (threadIdx.x == 0) {
            g_normE[k] = t;
            if (blockIdx.x == 0) g_loss = 0.0;
        }
    }
}

// ================= Kernel 2: transpose z -> zt (f32 + bf16) =====================
__global__ void transpose_k(const float* __restrict__ z) {
    __shared__ float tile[32][33];
    int b  = blockIdx.z;
    int p0 = blockIdx.x * 32;
    int d0 = blockIdx.y * 32;
    const float* src = z + (size_t)b * DIM * HW;
    #pragma unroll
    for (int i = 0; i < 32; i += 8)
        tile[threadIdx.y + i][threadIdx.x] = src[(d0 + threadIdx.y + i) * HW + p0 + threadIdx.x];
    __syncthreads();
    #pragma unroll
    for (int i = 0; i < 32; i += 8) {
        float v = tile[threadIdx.x][threadIdx.y + i];
        int o = (b * HW + p0 + threadIdx.y + i) * DIM + d0 + threadIdx.x;
        g_zt[o]  = v;
        g_zth[o] = __float2bfloat16(v);
    }
}

// ================= Kernel 2b: t1 = sequential sum of z_d^2 ======================
__global__ __launch_bounds__(256) void rownorm_k() {
    __shared__ float srow[32 * 257];
    int base = blockIdx.x * 32;
    for (int idx = threadIdx.x; idx < 32 * 256; idx += 256) {
        int r = idx >> 8, c = idx & 255;
        srow[r * 257 + c] = g_zt[(base + r) * DIM + c];
    }
    __syncthreads();
    if (threadIdx.x < 32) {
        const float* row = &srow[threadIdx.x * 257];
        float acc = 0.0f;
        #pragma unroll 8
        for (int d = 0; d < 256; d++)
            acc = __fadd_rn(acc, __fmul_rn(row[d], row[d]));
        g_t1[base + threadIdx.x] = acc;
    }
}

// ================= Kernel 3: HMMA bf16 GEMM + approx top-3/slot =================
// smem: A 64KB | B0 64KB | B1 64KB  (192KB dynamic)
#define AS_OFF 0
#define BS_OFF 65536
#define HM_SMEM 196608

__global__ __launch_bounds__(256, 1) void gemm_hmma_k() {
    extern __shared__ char smem[];
    const uint32_t sb = smem_u32(smem);
    const int tid  = threadIdx.x;
    const int lane = tid & 31;
    const int wid  = tid >> 5;
    const int wm   = wid & 1;        // 2 warps over M (64 rows each)
    const int wn   = wid >> 1;       // 4 warps over N (32 codes each)
    const int m0   = blockIdx.x * 128;

    // ---- prologue: cp.async A + B0 (group G0), B1 (group G1) ----
    #pragma unroll 4
    for (int i = tid; i < 4096; i += 256) {
        int row = i >> 5, c16 = i & 31;
        const __nv_bfloat16* src = &g_zth[(size_t)(m0 + row) * DIM + c16 * 8];
        CP_ASYNC16(sb + AS_OFF + sw_off(row, c16), (const void*)src);
    }
    #pragma unroll 4
    for (int i = tid; i < 4096; i += 256) {
        int row = i >> 5, c16 = i & 31;
        const __nv_bfloat16* src = &g_cbh[(size_t)row * DIM + c16 * 8];
        CP_ASYNC16(sb + BS_OFF + sw_off(row, c16), (const void*)src);
    }
    CP_COMMIT();
    #pragma unroll 4
    for (int i = tid; i < 4096; i += 256) {
        int row = i >> 5, c16 = i & 31;
        const __nv_bfloat16* src = &g_cbh[(size_t)(128 + row) * DIM + c16 * 8];
        CP_ASYNC16(sb + BS_OFF + 65536 + sw_off(row, c16), (const void*)src);
    }
    CP_COMMIT();

    // top-3 per slot: slots = mt*2 + h (8 row-slots per thread)
    float tv[8][NSLOT];
    int   ts[8][NSLOT];
    #pragma unroll
    for (int s = 0; s < 8; s++)
        #pragma unroll
        for (int j = 0; j < NSLOT; j++) { tv[s][j] = 3.4e38f; ts[s][j] = 0; }

    for (int c = 0; c < 8; ++c) {
        if (c < 7) CP_WAIT1(); else CP_WAIT0();
        __syncthreads();

        const uint32_t Bbase = sb + BS_OFF + ((c & 1) << 16);
        float C[4][4][4];
        #pragma unroll
        for (int mt = 0; mt < 4; mt++)
            #pragma unroll
            for (int nt = 0; nt < 4; nt++)
                #pragma unroll
                for (int q = 0; q < 4; q++) C[mt][nt][q] = 0.0f;

        #pragma unroll
        for (int st = 0; st < 16; ++st) {
            uint32_t a[4][4];
            #pragma unroll
            for (int mt = 0; mt < 4; mt++) {
                int row = wm * 64 + mt * 16 + (lane & 15);
                int c16 = st * 2 + (lane >> 4);
                LDSM4(a[mt][0], a[mt][1], a[mt][2], a[mt][3], sb + AS_OFF + sw_off(row, c16));
            }
            uint32_t b[2][4];
            #pragma unroll
            for (int p = 0; p < 2; p++) {
                int row = wn * 32 + p * 16 + ((lane >> 4) & 1) * 8 + (lane & 7);
                int c16 = st * 2 + ((lane >> 3) & 1);
                LDSM4(b[p][0], b[p][1], b[p][2], b[p][3], Bbase + sw_off(row, c16));
            }
            #pragma unroll
            for (int mt = 0; mt < 4; mt++)
                #pragma unroll
                for (int nt = 0; nt < 4; nt++)
                    MMA16816(C[mt][nt], a[mt], b[nt >> 1][(nt & 1) * 2], b[nt >> 1][(nt & 1) * 2 + 1]);
        }
        __syncthreads();   // all warps done reading buf[c&1]

        // prefetch chunk c+2 into buf[c&1] (overlaps with epilogue)
        if (c + 2 < 8) {
            #pragma unroll 4
            for (int i = tid; i < 4096; i += 256) {
                int row = i >> 5, c16 = i & 31;
                const __nv_bfloat16* src = &g_cbh[(size_t)((c + 2) * 128 + row) * DIM + c16 * 8];
                CP_ASYNC16(Bbase + sw_off(row, c16), (const void*)src);
            }
            CP_COMMIT();
        }

        // epilogue: dist = ne - 2*dot, update top-3 per row-slot
        #pragma unroll
        for (int mt = 0; mt < 4; mt++) {
            #pragma unroll
            for (int nt = 0; nt < 4; nt++) {
                int col = c * 128 + wn * 32 + nt * 8 + ((lane & 3) << 1);
                float ne0 = __ldg(&g_normE[col]);
                float ne1 = __ldg(&g_normE[col + 1]);
                float dv[4];
                dv[0] = __fmaf_rn(-2.0f, C[mt][nt][0], ne0);
                dv[1] = __fmaf_rn(-2.0f, C[mt][nt][1], ne1);
                dv[2] = __fmaf_rn(-2.0f, C[mt][nt][2], ne0);
                dv[3] = __fmaf_rn(-2.0f, C[mt][nt][3], ne1);
                #pragma unroll
                for (int q = 0; q < 4; q++) {
                    const int s = mt * 2 + (q >> 1);
                    const int idx = col + (q & 1);
                    const float v = dv[q];
                    if (v < tv[s][2]) {
                        if (v < tv[s][1]) {
                            tv[s][2] = tv[s][1]; ts[s][2] = ts[s][1];
                            if (v < tv[s][0]) {
                                tv[s][1] = tv[s][0]; ts[s][1] = ts[s][0];
                                tv[s][0] = v;        ts[s][0] = idx;
                            } else { tv[s][1] = v; ts[s][1] = idx; }
                        } else { tv[s][2] = v; ts[s][2] = idx; }
                    }
                }
            }
        }
    }

    // write candidates: row owned by 16 threads (4 n-warps x 4 lane%4), 3 each
    #pragma unroll
    for (int mt = 0; mt < 4; mt++) {
        #pragma unroll
        for (int h = 0; h < 2; h++) {
            int row  = m0 + wm * 64 + mt * 16 + h * 8 + (lane >> 2);
            int slot = wn * 4 + (lane & 3);
            int s = mt * 2 + h;
            #pragma unroll
            for (int j = 0; j < NSLOT; j++) {
                g_candV[(size_t)row * NCROW + slot * NSLOT + j] = tv[s][j];
                g_candI[(size_t)row * NCROW + slot * NSLOT + j] = ts[s][j];
            }
        }
    }
}

// ================= Kernel 3b: exact fp32 rescore (R2's summation order) =========
__global__ __launch_bounds__(256) void rescore_k(const float* __restrict__ cb) {
    int row = blockIdx.x * 256 + threadIdx.x;
    const float* cv = &g_candV[(size_t)row * NCROW];
    const int*   ci = &g_candI[(size_t)row * NCROW];

    float vmin = 3.4e38f;
    #pragma unroll 8
    for (int j = 0; j < NCROW; j++) vmin = fminf(vmin, cv[j]);
    const float thr = vmin + MARGIN;
    const float t1 = g_t1[row];
    const float* zrow = &g_zt[(size_t)row * DIM];

    float bestD = 3.4e38f;
    int   bestI = 0x7fffffff;
    for (int j = 0; j < NCROW; j++) {
        if (cv[j] > thr) continue;
        int idx = ci[j];
        const float* crow = &cb[(size_t)idx * DIM];
        // sequential d=0..255 fp32 FMA chain == R2's passing accumulation order
        float p = 0.0f;
        #pragma unroll 8
        for (int d = 0; d < 256; d++) p = __fmaf_rn(zrow[d], crow[d], p);
        float dd = __fsub_rn(__fadd_rn(t1, __ldg(&g_normE[idx])), __fmul_rn(2.0f, p));
        if (dd < bestD || (dd == bestD && idx < bestI)) { bestD = dd; bestI = idx; }
    }
    g_idx[row] = bestI;
}

// ================= Kernel 4: straight-through z_q + loss ========================
__global__ void gather_loss_k(const float* __restrict__ z, const float* __restrict__ cb,
                              float* __restrict__ out) {
    int i = blockIdx.x * 256 + threadIdx.x;
    int p = i & (HW - 1);
    int d = (i >> 10) & (DIM - 1);
    int b = i >> 18;
    int n = (b << 10) | p;
    float zv = z[i];
    float q  = cb[g_idx[n] * DIM + d];
    float diff = __fsub_rn(q, zv);
    out[i] = __fadd_rn(zv, diff);
    float sq = __fmul_rn(diff, diff);

    __shared__ float s[8];
    float vv = sq;
    #pragma unroll
    for (int o = 16; o; o >>= 1) vv += __shfl_down_sync(0xffffffffu, vv, o);
    if ((threadIdx.x & 31) == 0) s[threadIdx.x >> 5] = vv;
    __syncthreads();
    if (threadIdx.x < 8) {
        float t = s[threadIdx.x];
        #pragma unroll
        for (int o = 4; o; o >>= 1) t += __shfl_down_sync(0xffu, t, o);
        if (threadIdx.x == 0) atomicAdd(&g_loss, (double)t);
    }
}

// ================= Kernel 5: idx + loss finalize ================================
__global__ void finalize_k(float* __restrict__ out, int write_loss) {
    int t = blockIdx.x * 256 + threadIdx.x;
    if (t < NPTS) out[IDX_OFF + t] = (float)g_idx[t];
    if (t == 0 && write_loss)
        out[LOSS_OFF] = (float)(1.25 * g_loss / (double)ZQ_ELEMS);
}

extern "C" void kernel_launch(void* const* d_in, const int* in_sizes, int n_in,
                              void* d_out, int out_size) {
    const float* z  = (const float*)d_in[0];
    const float* cb = (const float*)d_in[1];
    float* out = (float*)d_out;

    static int smem_set = 0;
    if (!smem_set) {
        cudaFuncSetAttribute(gemm_hmma_k, cudaFuncAttributeMaxDynamicSharedMemorySize, HM_SMEM);
        smem_set = 1;
    }

    norms_k<<<KCODE, 256>>>(cb);
    transpose_k<<<dim3(HW / 32, DIM / 32, BATCH), dim3(32, 8)>>>(z);
    rownorm_k<<<NPTS / 32, 256>>>();
    gemm_hmma_k<<<NPTS / 128, 256, HM_SMEM>>>();
    rescore_k<<<NPTS / 256, 256>>>(cb);
    gather_loss_k<<<ZQ_ELEMS / 256, 256>>>(z, cb, out);

    int write_idx  = (out_size >= IDX_OFF + NPTS);
    int write_loss = (out_size >= LOSS_OFF + 1);
    if (write_idx) finalize_k<<<NPTS / 256, 256>>>(out, write_loss);
}

// round 5
// speedup vs baseline: 3.1166x; 1.8690x over previous
#include <cuda_runtime.h>
#include <cuda_bf16.h>
#include <cstdint>

// Problem constants
#define BATCH 32
#define DIM   256
#define HW    1024
#define NPTS  32768
#define KCODE 1024
#define ZQ_ELEMS 8388608
#define IDX_OFF  ZQ_ELEMS
#define LOSS_OFF (ZQ_ELEMS + NPTS)

#define NSLOT 3           // top-3 per (thread,row) slot
#define NCROW 48          // 16 slots * 3 candidates per row
#define MARGIN 7e-4f

// Scratch (device globals)
__device__ float          g_zt [NPTS * DIM];     // z^T fp32 [N,D]
__device__ __nv_bfloat16  g_zth[NPTS * DIM];     // z^T bf16
__device__ __nv_bfloat16  g_cbh[KCODE * DIM];    // codebook bf16
__device__ int            g_idx[NPTS];
__device__ float          g_normE[KCODE];        // t2
__device__ float          g_t1[NPTS];            // t1 (sequential emulation)
__device__ float          g_candV[NPTS * NCROW];
__device__ int            g_candI[NPTS * NCROW];
__device__ double         g_loss;

// ================= generic PTX helpers =================
__device__ __forceinline__ uint32_t smem_u32(const void* p) {
    uint32_t a;
    asm("{ .reg .u64 t; cvta.to.shared.u64 t, %1; cvt.u32.u64 %0, t; }" : "=r"(a) : "l"(p));
    return a;
}
#define CP_ASYNC16(dst, src) \
    asm volatile("cp.async.cg.shared.global [%0], [%1], 16;" :: "r"(dst), "l"(src) : "memory")
#define CP_COMMIT() asm volatile("cp.async.commit_group;" ::: "memory")
#define CP_WAIT0()  asm volatile("cp.async.wait_group 0;" ::: "memory")
#define CP_WAIT1()  asm volatile("cp.async.wait_group 1;" ::: "memory")

#define LDSM4(r0, r1, r2, r3, addr) \
    asm volatile("ldmatrix.sync.aligned.m8n8.x4.shared.b16 {%0,%1,%2,%3}, [%4];" \
        : "=r"(r0), "=r"(r1), "=r"(r2), "=r"(r3) : "r"(addr))

#define MMA16816(C, A, b0, b1) \
    asm volatile("mma.sync.aligned.m16n8k16.row.col.f32.bf16.bf16.f32 " \
        "{%0,%1,%2,%3},{%4,%5,%6,%7},{%8,%9},{%0,%1,%2,%3};" \
        : "+f"((C)[0]), "+f"((C)[1]), "+f"((C)[2]), "+f"((C)[3]) \
        : "r"((A)[0]), "r"((A)[1]), "r"((A)[2]), "r"((A)[3]), "r"(b0), "r"(b1))

// swizzled smem offset for bf16 tile [128 rows][256 cols], 512B/row, 16B chunks
__device__ __forceinline__ uint32_t sw_off(int row, int c16) {
    return (uint32_t)(row * 512 + ((c16 ^ (row & 7)) << 4));
}

// ================= Kernel 1: codebook norms + bf16 cvt + loss reset =============
__global__ void norms_k(const float* __restrict__ cb) {
    int k = blockIdx.x;
    float x = cb[k * DIM + threadIdx.x];
    g_cbh[k * DIM + threadIdx.x] = __float2bfloat16(x);
    float v = __fmul_rn(x, x);
    __shared__ float s[8];
    #pragma unroll
    for (int o = 16; o; o >>= 1) v += __shfl_down_sync(0xffffffffu, v, o);
    if ((threadIdx.x & 31) == 0) s[threadIdx.x >> 5] = v;
    __syncthreads();
    if (threadIdx.x < 8) {
        float t = s[threadIdx.x];
        #pragma unroll
        for (int o = 4; o; o >>= 1) t += __shfl_down_sync(0xffu, t, o);
        if (threadIdx.x == 0) {
            g_normE[k] = t;
            if (blockIdx.x == 0) g_loss = 0.0;
        }
    }
}

// ================= Kernel 2: transpose z -> zt (f32 + bf16) =====================
__global__ void transpose_k(const float* __restrict__ z) {
    __shared__ float tile[32][33];
    int b  = blockIdx.z;
    int p0 = blockIdx.x * 32;
    int d0 = blockIdx.y * 32;
    const float* src = z + (size_t)b * DIM * HW;
    #pragma unroll
    for (int i = 0; i < 32; i += 8)
        tile[threadIdx.y + i][threadIdx.x] = src[(d0 + threadIdx.y + i) * HW + p0 + threadIdx.x];
    __syncthreads();
    #pragma unroll
    for (int i = 0; i < 32; i += 8) {
        float v = tile[threadIdx.x][threadIdx.y + i];
        int o = (b * HW + p0 + threadIdx.y + i) * DIM + d0 + threadIdx.x;
        g_zt[o]  = v;
        g_zth[o] = __float2bfloat16(v);
    }
}

// ================= Kernel 2b: t1 from ORIGINAL z layout (coalesced, seq order) ==
__global__ __launch_bounds__(256) void rownorm_z_k(const float* __restrict__ z) {
    int b = blockIdx.x >> 2;
    int p = ((blockIdx.x & 3) << 8) + threadIdx.x;
    const float* src = z + (size_t)b * DIM * HW + p;
    float acc = 0.0f;
    #pragma unroll 8
    for (int d = 0; d < 256; d++) {
        float x = src[(size_t)d * HW];
        acc = __fadd_rn(acc, __fmul_rn(x, x));   // strict d=0..255 sequential chain
    }
    g_t1[(b << 10) + p] = acc;
}

// ================= Kernel 3: HMMA bf16 GEMM + approx top-3/slot (UNCHANGED) =====
#define AS_OFF 0
#define BS_OFF 65536
#define HM_SMEM 196608

__global__ __launch_bounds__(256, 1) void gemm_hmma_k() {
    extern __shared__ char smem[];
    const uint32_t sb = smem_u32(smem);
    const int tid  = threadIdx.x;
    const int lane = tid & 31;
    const int wid  = tid >> 5;
    const int wm   = wid & 1;
    const int wn   = wid >> 1;
    const int m0   = blockIdx.x * 128;

    #pragma unroll 4
    for (int i = tid; i < 4096; i += 256) {
        int row = i >> 5, c16 = i & 31;
        const __nv_bfloat16* src = &g_zth[(size_t)(m0 + row) * DIM + c16 * 8];
        CP_ASYNC16(sb + AS_OFF + sw_off(row, c16), (const void*)src);
    }
    #pragma unroll 4
    for (int i = tid; i < 4096; i += 256) {
        int row = i >> 5, c16 = i & 31;
        const __nv_bfloat16* src = &g_cbh[(size_t)row * DIM + c16 * 8];
        CP_ASYNC16(sb + BS_OFF + sw_off(row, c16), (const void*)src);
    }
    CP_COMMIT();
    #pragma unroll 4
    for (int i = tid; i < 4096; i += 256) {
        int row = i >> 5, c16 = i & 31;
        const __nv_bfloat16* src = &g_cbh[(size_t)(128 + row) * DIM + c16 * 8];
        CP_ASYNC16(sb + BS_OFF + 65536 + sw_off(row, c16), (const void*)src);
    }
    CP_COMMIT();

    float tv[8][NSLOT];
    int   ts[8][NSLOT];
    #pragma unroll
    for (int s = 0; s < 8; s++)
        #pragma unroll
        for (int j = 0; j < NSLOT; j++) { tv[s][j] = 3.4e38f; ts[s][j] = 0; }

    for (int c = 0; c < 8; ++c) {
        if (c < 7) CP_WAIT1(); else CP_WAIT0();
        __syncthreads();

        const uint32_t Bbase = sb + BS_OFF + ((c & 1) << 16);
        float C[4][4][4];
        #pragma unroll
        for (int mt = 0; mt < 4; mt++)
            #pragma unroll
            for (int nt = 0; nt < 4; nt++)
                #pragma unroll
                for (int q = 0; q < 4; q++) C[mt][nt][q] = 0.0f;

        #pragma unroll
        for (int st = 0; st < 16; ++st) {
            uint32_t a[4][4];
            #pragma unroll
            for (int mt = 0; mt < 4; mt++) {
                int row = wm * 64 + mt * 16 + (lane & 15);
                int c16 = st * 2 + (lane >> 4);
                LDSM4(a[mt][0], a[mt][1], a[mt][2], a[mt][3], sb + AS_OFF + sw_off(row, c16));
            }
            uint32_t b[2][4];
            #pragma unroll
            for (int p = 0; p < 2; p++) {
                int row = wn * 32 + p * 16 + ((lane >> 4) & 1) * 8 + (lane & 7);
                int c16 = st * 2 + ((lane >> 3) & 1);
                LDSM4(b[p][0], b[p][1], b[p][2], b[p][3], Bbase + sw_off(row, c16));
            }
            #pragma unroll
            for (int mt = 0; mt < 4; mt++)
                #pragma unroll
                for (int nt = 0; nt < 4; nt++)
                    MMA16816(C[mt][nt], a[mt], b[nt >> 1][(nt & 1) * 2], b[nt >> 1][(nt & 1) * 2 + 1]);
        }
        __syncthreads();

        if (c + 2 < 8) {
            #pragma unroll 4
            for (int i = tid; i < 4096; i += 256) {
                int row = i >> 5, c16 = i & 31;
                const __nv_bfloat16* src = &g_cbh[(size_t)((c + 2) * 128 + row) * DIM + c16 * 8];
                CP_ASYNC16(Bbase + sw_off(row, c16), (const void*)src);
            }
            CP_COMMIT();
        }

        #pragma unroll
        for (int mt = 0; mt < 4; mt++) {
            #pragma unroll
            for (int nt = 0; nt < 4; nt++) {
                int col = c * 128 + wn * 32 + nt * 8 + ((lane & 3) << 1);
                float ne0 = __ldg(&g_normE[col]);
                float ne1 = __ldg(&g_normE[col + 1]);
                float dv[4];
                dv[0] = __fmaf_rn(-2.0f, C[mt][nt][0], ne0);
                dv[1] = __fmaf_rn(-2.0f, C[mt][nt][1], ne1);
                dv[2] = __fmaf_rn(-2.0f, C[mt][nt][2], ne0);
                dv[3] = __fmaf_rn(-2.0f, C[mt][nt][3], ne1);
                #pragma unroll
                for (int q = 0; q < 4; q++) {
                    const int s = mt * 2 + (q >> 1);
                    const int idx = col + (q & 1);
                    const float v = dv[q];
                    if (v < tv[s][2]) {
                        if (v < tv[s][1]) {
                            tv[s][2] = tv[s][1]; ts[s][2] = ts[s][1];
                            if (v < tv[s][0]) {
                                tv[s][1] = tv[s][0]; ts[s][1] = ts[s][0];
                                tv[s][0] = v;        ts[s][0] = idx;
                            } else { tv[s][1] = v; ts[s][1] = idx; }
                        } else { tv[s][2] = v; ts[s][2] = idx; }
                    }
                }
            }
        }
    }

    #pragma unroll
    for (int mt = 0; mt < 4; mt++) {
        #pragma unroll
        for (int h = 0; h < 2; h++) {
            int row  = m0 + wm * 64 + mt * 16 + h * 8 + (lane >> 2);
            int slot = wn * 4 + (lane & 3);
            int s = mt * 2 + h;
            #pragma unroll
            for (int j = 0; j < NSLOT; j++) {
                g_candV[(size_t)row * NCROW + slot * NSLOT + j] = tv[s][j];
                g_candI[(size_t)row * NCROW + slot * NSLOT + j] = ts[s][j];
            }
        }
    }
}

// ================= Kernel 3b: warp-per-row exact rescore ========================
__global__ __launch_bounds__(256) void rescore_k(const float* __restrict__ cb) {
    const int wid  = threadIdx.x >> 5;
    const int lane = threadIdx.x & 31;
    const int row  = blockIdx.x * 8 + wid;
    const float* cv = &g_candV[(size_t)row * NCROW];
    const int*   ci = &g_candI[(size_t)row * NCROW];

    float v1 = cv[lane];
    float v2 = (lane < 16) ? cv[32 + lane] : 3.4e38f;
    int   i1 = ci[lane];
    int   i2 = (lane < 16) ? ci[32 + lane] : 0;

    float vmin = fminf(v1, v2);
    #pragma unroll
    for (int o = 16; o; o >>= 1) vmin = fminf(vmin, __shfl_xor_sync(0xffffffffu, vmin, o));
    const float thr = vmin + MARGIN;

    unsigned m1 = __ballot_sync(0xffffffffu, v1 <= thr);
    unsigned m2 = __ballot_sync(0xffffffffu, v2 <= thr);

    if (__popc(m1) + __popc(m2) == 1) {
        // unique candidate within margin: bf16 error << MARGIN, so it is the
        // exact argmin and no reference-tie is possible. Skip the dot.
        int idx;
        if (m1) idx = __shfl_sync(0xffffffffu, i1, __ffs(m1) - 1);
        else    idx = __shfl_sync(0xffffffffu, i2, __ffs(m2) - 1);
        if (lane == 0) g_idx[row] = idx;
        return;
    }

    // exact fp32 rescore, warp-parallel coalesced
    const float4* zp = (const float4*)&g_zt[(size_t)row * DIM + lane * 8];
    const float4 za = zp[0], zb = zp[1];
    const float t1 = g_t1[row];

    float bestD = 3.4e38f;
    int   bestI = 0x7fffffff;
    while (m1 | m2) {
        int idx;
        if (m1) { int l = __ffs(m1) - 1; m1 &= m1 - 1; idx = __shfl_sync(0xffffffffu, i1, l); }
        else    { int l = __ffs(m2) - 1; m2 &= m2 - 1; idx = __shfl_sync(0xffffffffu, i2, l); }
        const float4* cp = (const float4*)&cb[(size_t)idx * DIM + lane * 8];
        float4 ca = cp[0], cb4 = cp[1];
        float p = 0.0f;
        p = __fmaf_rn(za.x, ca.x, p);  p = __fmaf_rn(za.y, ca.y, p);
        p = __fmaf_rn(za.z, ca.z, p);  p = __fmaf_rn(za.w, ca.w, p);
        p = __fmaf_rn(zb.x, cb4.x, p); p = __fmaf_rn(zb.y, cb4.y, p);
        p = __fmaf_rn(zb.z, cb4.z, p); p = __fmaf_rn(zb.w, cb4.w, p);
        #pragma unroll
        for (int o = 16; o; o >>= 1) p += __shfl_xor_sync(0xffffffffu, p, o);
        float dd = __fsub_rn(__fadd_rn(t1, __ldg(&g_normE[idx])), __fmul_rn(2.0f, p));
        if (dd < bestD || (dd == bestD && idx < bestI)) { bestD = dd; bestI = idx; }
    }
    if (lane == 0) g_idx[row] = bestI;
}

// ================= Kernel 4: straight-through z_q + loss (grid-stride) ==========
#define GL_BLOCKS 4096
__global__ __launch_bounds__(256) void gather_loss_k(const float* __restrict__ z,
                                                     const float* __restrict__ cb,
                                                     float* __restrict__ out) {
    float local = 0.0f;
    for (int i = blockIdx.x * 256 + threadIdx.x; i < ZQ_ELEMS; i += GL_BLOCKS * 256) {
        int p = i & (HW - 1);
        int d = (i >> 10) & (DIM - 1);
        int b = i >> 18;
        int n = (b << 10) | p;
        float zv = z[i];
        float q  = cb[g_idx[n] * DIM + d];
        float diff = __fsub_rn(q, zv);
        out[i] = __fadd_rn(zv, diff);
        local = __fmaf_rn(diff, diff, local);
    }
    __shared__ float s[8];
    #pragma unroll
    for (int o = 16; o; o >>= 1) local += __shfl_down_sync(0xffffffffu, local, o);
    if ((threadIdx.x & 31) == 0) s[threadIdx.x >> 5] = local;
    __syncthreads();
    if (threadIdx.x < 8) {
        float t = s[threadIdx.x];
        #pragma unroll
        for (int o = 4; o; o >>= 1) t += __shfl_down_sync(0xffu, t, o);
        if (threadIdx.x == 0) atomicAdd(&g_loss, (double)t);
    }
}

// ================= Kernel 5: idx + loss finalize ================================
__global__ void finalize_k(float* __restrict__ out, int write_loss) {
    int t = blockIdx.x * 256 + threadIdx.x;
    if (t < NPTS) out[IDX_OFF + t] = (float)g_idx[t];
    if (t == 0 && write_loss)
        out[LOSS_OFF] = (float)(1.25 * g_loss / (double)ZQ_ELEMS);
}

extern "C" void kernel_launch(void* const* d_in, const int* in_sizes, int n_in,
                              void* d_out, int out_size) {
    const float* z  = (const float*)d_in[0];
    const float* cb = (const float*)d_in[1];
    float* out = (float*)d_out;

    cudaFuncSetAttribute(gemm_hmma_k, cudaFuncAttributeMaxDynamicSharedMemorySize, HM_SMEM);

    norms_k<<<KCODE, 256>>>(cb);
    transpose_k<<<dim3(HW / 32, DIM / 32, BATCH), dim3(32, 8)>>>(z);
    rownorm_z_k<<<BATCH * 4, 256>>>(z);
    gemm_hmma_k<<<NPTS / 128, 256, HM_SMEM>>>();
    rescore_k<<<NPTS / 8, 256>>>(cb);
    gather_loss_k<<<GL_BLOCKS, 256>>>(z, cb, out);

    int write_idx  = (out_size >= IDX_OFF + NPTS);
    int write_loss = (out_size >= LOSS_OFF + 1);
    if (write_idx) finalize_k<<<NPTS / 256, 256>>>(out, write_loss);
}

// round 6
// speedup vs baseline: 3.1602x; 1.0140x over previous
#include <cuda_runtime.h>
#include <cuda_bf16.h>
#include <cstdint>

// Problem constants
#define BATCH 32
#define DIM   256
#define HW    1024
#define NPTS  32768
#define KCODE 1024
#define ZQ_ELEMS 8388608
#define IDX_OFF  ZQ_ELEMS
#define LOSS_OFF (ZQ_ELEMS + NPTS)

#define NSLOT 3           // top-3 per (thread,row) slot
#define NCROW 24          // 8 slots * 3 candidates per row
#define MARGIN 7e-4f

// Scratch (device globals)
__device__ float          g_zt [NPTS * DIM];     // z^T fp32 [N,D]
__device__ __nv_bfloat16  g_zth[NPTS * DIM];     // z^T bf16
__device__ __nv_bfloat16  g_cbh[KCODE * DIM];    // codebook bf16
__device__ int            g_idx[NPTS];
__device__ float          g_normE[KCODE];        // t2
__device__ float          g_t1[NPTS];            // t1 (sequential emulation)
__device__ float          g_candV[NPTS * NCROW];
__device__ int            g_candI[NPTS * NCROW];
__device__ double         g_loss;
__device__ unsigned       g_done;                // zero-init; reset after use

// ================= generic PTX helpers =================
__device__ __forceinline__ uint32_t smem_u32(const void* p) {
    uint32_t a;
    asm("{ .reg .u64 t; cvta.to.shared.u64 t, %1; cvt.u32.u64 %0, t; }" : "=r"(a) : "l"(p));
    return a;
}
#define CP_ASYNC16(dst, src) \
    asm volatile("cp.async.cg.shared.global [%0], [%1], 16;" :: "r"(dst), "l"(src) : "memory")
#define CP_COMMIT() asm volatile("cp.async.commit_group;" ::: "memory")
#define CP_WAIT0()  asm volatile("cp.async.wait_group 0;" ::: "memory")
#define CP_WAIT1()  asm volatile("cp.async.wait_group 1;" ::: "memory")

#define LDSM4(r0, r1, r2, r3, addr) \
    asm volatile("ldmatrix.sync.aligned.m8n8.x4.shared.b16 {%0,%1,%2,%3}, [%4];" \
        : "=r"(r0), "=r"(r1), "=r"(r2), "=r"(r3) : "r"(addr))

#define MMA16816(C, A, b0, b1) \
    asm volatile("mma.sync.aligned.m16n8k16.row.col.f32.bf16.bf16.f32 " \
        "{%0,%1,%2,%3},{%4,%5,%6,%7},{%8,%9},{%0,%1,%2,%3};" \
        : "+f"((C)[0]), "+f"((C)[1]), "+f"((C)[2]), "+f"((C)[3]) \
        : "r"((A)[0]), "r"((A)[1]), "r"((A)[2]), "r"((A)[3]), "r"(b0), "r"(b1))

// swizzled smem offset for bf16 tile rows of 512B, 16B chunks
__device__ __forceinline__ uint32_t sw_off(int row, int c16) {
    return (uint32_t)(row * 512 + ((c16 ^ (row & 7)) << 4));
}

// ================= Kernel 1: codebook norms + bf16 cvt + loss reset =============
__global__ void norms_k(const float* __restrict__ cb) {
    int k = blockIdx.x;
    float x = cb[k * DIM + threadIdx.x];
    g_cbh[k * DIM + threadIdx.x] = __float2bfloat16(x);
    float v = __fmul_rn(x, x);
    __shared__ float s[8];
    #pragma unroll
    for (int o = 16; o; o >>= 1) v += __shfl_down_sync(0xffffffffu, v, o);
    if ((threadIdx.x & 31) == 0) s[threadIdx.x >> 5] = v;
    __syncthreads();
    if (threadIdx.x < 8) {
        float t = s[threadIdx.x];
        #pragma unroll
        for (int o = 4; o; o >>= 1) t += __shfl_down_sync(0xffu, t, o);
        if (threadIdx.x == 0) {
            g_normE[k] = t;
            if (blockIdx.x == 0) g_loss = 0.0;
        }
    }
}

// ================= Kernel 2: transpose z -> zt (f32 + bf16) =====================
__global__ void transpose_k(const float* __restrict__ z) {
    __shared__ float tile[32][33];
    int b  = blockIdx.z;
    int p0 = blockIdx.x * 32;
    int d0 = blockIdx.y * 32;
    const float* src = z + (size_t)b * DIM * HW;
    #pragma unroll
    for (int i = 0; i < 32; i += 8)
        tile[threadIdx.y + i][threadIdx.x] = src[(d0 + threadIdx.y + i) * HW + p0 + threadIdx.x];
    __syncthreads();
    #pragma unroll
    for (int i = 0; i < 32; i += 8) {
        float v = tile[threadIdx.x][threadIdx.y + i];
        int o = (b * HW + p0 + threadIdx.y + i) * DIM + d0 + threadIdx.x;
        g_zt[o]  = v;
        g_zth[o] = __float2bfloat16(v);
    }
}

// ================= Kernel 2b: t1 from original z layout (coalesced, seq order) ==
__global__ __launch_bounds__(256) void rownorm_z_k(const float* __restrict__ z) {
    int b = blockIdx.x >> 2;
    int p = ((blockIdx.x & 3) << 8) + threadIdx.x;
    const float* src = z + (size_t)b * DIM * HW + p;
    float acc = 0.0f;
    #pragma unroll 8
    for (int d = 0; d < 256; d++) {
        float x = src[(size_t)d * HW];
        acc = __fadd_rn(acc, __fmul_rn(x, x));   // strict d=0..255 sequential chain
    }
    g_t1[(b << 10) + p] = acc;
}

// ================= Kernel 3: HMMA bf16 GEMM, 2 CTAs/SM, 64-row tiles ============
// smem: A 32KB | B0 32KB | B1 32KB  (96KB dynamic) -> 2 CTAs/SM
#define AS_OFF 0
#define BS_OFF 32768
#define HM_SMEM 98304

__global__ __launch_bounds__(128, 2) void gemm_hmma_k() {
    extern __shared__ char smem[];
    const uint32_t sb = smem_u32(smem);
    const int tid  = threadIdx.x;
    const int lane = tid & 31;
    const int wid  = tid >> 5;       // 4 warps
    const int wm   = wid & 1;        // 2 warps over M (32 rows each)
    const int wn   = wid >> 1;       // 2 warps over N (32 codes each)
    const int m0   = blockIdx.x * 64;

    // ---- prologue: A (64 rows) + B chunk 0, then B chunk 1 ----
    #pragma unroll 4
    for (int i = tid; i < 2048; i += 128) {
        int row = i >> 5, c16 = i & 31;
        const __nv_bfloat16* src = &g_zth[(size_t)(m0 + row) * DIM + c16 * 8];
        CP_ASYNC16(sb + AS_OFF + sw_off(row, c16), (const void*)src);
    }
    #pragma unroll 4
    for (int i = tid; i < 2048; i += 128) {
        int row = i >> 5, c16 = i & 31;
        const __nv_bfloat16* src = &g_cbh[(size_t)row * DIM + c16 * 8];
        CP_ASYNC16(sb + BS_OFF + sw_off(row, c16), (const void*)src);
    }
    CP_COMMIT();
    #pragma unroll 4
    for (int i = tid; i < 2048; i += 128) {
        int row = i >> 5, c16 = i & 31;
        const __nv_bfloat16* src = &g_cbh[(size_t)(64 + row) * DIM + c16 * 8];
        CP_ASYNC16(sb + BS_OFF + 32768 + sw_off(row, c16), (const void*)src);
    }
    CP_COMMIT();

    // top-3 per slot: s = mt*2 + h (4 row-slots per thread)
    float tv[4][NSLOT];
    int   ts[4][NSLOT];
    #pragma unroll
    for (int s = 0; s < 4; s++)
        #pragma unroll
        for (int j = 0; j < NSLOT; j++) { tv[s][j] = 3.4e38f; ts[s][j] = 0; }

    for (int c = 0; c < 16; ++c) {
        if (c < 15) CP_WAIT1(); else CP_WAIT0();
        __syncthreads();

        const uint32_t Bbase = sb + BS_OFF + ((c & 1) << 15);
        float C[2][4][4];
        #pragma unroll
        for (int mt = 0; mt < 2; mt++)
            #pragma unroll
            for (int nt = 0; nt < 4; nt++)
                #pragma unroll
                for (int q = 0; q < 4; q++) C[mt][nt][q] = 0.0f;

        #pragma unroll
        for (int st = 0; st < 16; ++st) {
            uint32_t a[2][4];
            #pragma unroll
            for (int mt = 0; mt < 2; mt++) {
                int row = wm * 32 + mt * 16 + (lane & 15);
                int c16 = st * 2 + (lane >> 4);
                LDSM4(a[mt][0], a[mt][1], a[mt][2], a[mt][3], sb + AS_OFF + sw_off(row, c16));
            }
            uint32_t b[2][4];
            #pragma unroll
            for (int p = 0; p < 2; p++) {
                int row = wn * 32 + p * 16 + ((lane >> 4) & 1) * 8 + (lane & 7);
                int c16 = st * 2 + ((lane >> 3) & 1);
                LDSM4(b[p][0], b[p][1], b[p][2], b[p][3], Bbase + sw_off(row, c16));
            }
            #pragma unroll
            for (int mt = 0; mt < 2; mt++)
                #pragma unroll
                for (int nt = 0; nt < 4; nt++)
                    MMA16816(C[mt][nt], a[mt], b[nt >> 1][(nt & 1) * 2], b[nt >> 1][(nt & 1) * 2 + 1]);
        }
        __syncthreads();   // all warps done reading buf[c&1]

        // prefetch chunk c+2 into buf[c&1] (async; overlaps epilogue)
        if (c + 2 < 16) {
            #pragma unroll 4
            for (int i = tid; i < 2048; i += 128) {
                int row = i >> 5, c16 = i & 31;
                const __nv_bfloat16* src = &g_cbh[(size_t)((c + 2) * 64 + row) * DIM + c16 * 8];
                CP_ASYNC16(Bbase + sw_off(row, c16), (const void*)src);
            }
            CP_COMMIT();
        }

        // epilogue: dist = ne - 2*dot, top-3 per row-slot
        #pragma unroll
        for (int mt = 0; mt < 2; mt++) {
            #pragma unroll
            for (int nt = 0; nt < 4; nt++) {
                int col = c * 64 + wn * 32 + nt * 8 + ((lane & 3) << 1);
                float ne0 = __ldg(&g_normE[col]);
                float ne1 = __ldg(&g_normE[col + 1]);
                float dv[4];
                dv[0] = __fmaf_rn(-2.0f, C[mt][nt][0], ne0);
                dv[1] = __fmaf_rn(-2.0f, C[mt][nt][1], ne1);
                dv[2] = __fmaf_rn(-2.0f, C[mt][nt][2], ne0);
                dv[3] = __fmaf_rn(-2.0f, C[mt][nt][3], ne1);
                #pragma unroll
                for (int q = 0; q < 4; q++) {
                    const int s = mt * 2 + (q >> 1);
                    const int idx = col + (q & 1);
                    const float v = dv[q];
                    if (v < tv[s][2]) {
                        if (v < tv[s][1]) {
                            tv[s][2] = tv[s][1]; ts[s][2] = ts[s][1];
                            if (v < tv[s][0]) {
                                tv[s][1] = tv[s][0]; ts[s][1] = ts[s][0];
                                tv[s][0] = v;        ts[s][0] = idx;
                            } else { tv[s][1] = v; ts[s][1] = idx; }
                        } else { tv[s][2] = v; ts[s][2] = idx; }
                    }
                }
            }
        }
    }

    // write candidates: row owned by 8 threads (2 n-warps x 4 lane%4), 3 each
    #pragma unroll
    for (int mt = 0; mt < 2; mt++) {
        #pragma unroll
        for (int h = 0; h < 2; h++) {
            int row  = m0 + wm * 32 + mt * 16 + h * 8 + (lane >> 2);
            int slot = wn * 4 + (lane & 3);
            int s = mt * 2 + h;
            #pragma unroll
            for (int j = 0; j < NSLOT; j++) {
                g_candV[(size_t)row * NCROW + slot * NSLOT + j] = tv[s][j];
                g_candI[(size_t)row * NCROW + slot * NSLOT + j] = ts[s][j];
            }
        }
    }
}

// ================= Kernel 3b: warp-per-row exact rescore + idx output ===========
__global__ __launch_bounds__(256) void rescore_k(const float* __restrict__ cb,
                                                 float* __restrict__ out, int write_idx) {
    const int wid  = threadIdx.x >> 5;
    const int lane = threadIdx.x & 31;
    const int row  = blockIdx.x * 8 + wid;
    const float* cv = &g_candV[(size_t)row * NCROW];
    const int*   ci = &g_candI[(size_t)row * NCROW];

    float v1 = (lane < NCROW) ? cv[lane] : 3.4e38f;
    int   i1 = (lane < NCROW) ? ci[lane] : 0;

    float vmin = v1;
    #pragma unroll
    for (int o = 16; o; o >>= 1) vmin = fminf(vmin, __shfl_xor_sync(0xffffffffu, vmin, o));
    const float thr = vmin + MARGIN;

    unsigned m1 = __ballot_sync(0xffffffffu, v1 <= thr);

    int bestI;
    if (__popc(m1) == 1) {
        // unique candidate within margin: bf16 error << MARGIN => exact argmin.
        bestI = __shfl_sync(0xffffffffu, i1, __ffs(m1) - 1);
    } else {
        const float4* zp = (const float4*)&g_zt[(size_t)row * DIM + lane * 8];
        const float4 za = zp[0], zb = zp[1];
        const float t1 = g_t1[row];
        float bestD = 3.4e38f;
        bestI = 0x7fffffff;
        while (m1) {
            int l = __ffs(m1) - 1; m1 &= m1 - 1;
            int idx = __shfl_sync(0xffffffffu, i1, l);
            const float4* cp = (const float4*)&cb[(size_t)idx * DIM + lane * 8];
            float4 ca = cp[0], cb4 = cp[1];
            float p = 0.0f;
            p = __fmaf_rn(za.x, ca.x, p);  p = __fmaf_rn(za.y, ca.y, p);
            p = __fmaf_rn(za.z, ca.z, p);  p = __fmaf_rn(za.w, ca.w, p);
            p = __fmaf_rn(zb.x, cb4.x, p); p = __fmaf_rn(zb.y, cb4.y, p);
            p = __fmaf_rn(zb.z, cb4.z, p); p = __fmaf_rn(zb.w, cb4.w, p);
            #pragma unroll
            for (int o = 16; o; o >>= 1) p += __shfl_xor_sync(0xffffffffu, p, o);
            float dd = __fsub_rn(__fadd_rn(t1, __ldg(&g_normE[idx])), __fmul_rn(2.0f, p));
            if (dd < bestD || (dd == bestD && idx < bestI)) { bestD = dd; bestI = idx; }
        }
        bestI = __shfl_sync(0xffffffffu, bestI, 0);
    }
    if (lane == 0) {
        g_idx[row] = bestI;
        if (write_idx) out[IDX_OFF + row] = (float)bestI;
    }
}

// ================= Kernel 4: straight-through z_q + loss + last-block finalize ==
#define GL_BLOCKS 4096
__global__ __launch_bounds__(256) void gather_loss_k(const float* __restrict__ z,
                                                     const float* __restrict__ cb,
                                                     float* __restrict__ out,
                                                     int write_loss) {
    float local = 0.0f;
    for (int i = blockIdx.x * 256 + threadIdx.x; i < ZQ_ELEMS; i += GL_BLOCKS * 256) {
        int p = i & (HW - 1);
        int d = (i >> 10) & (DIM - 1);
        int b = i >> 18;
        int n = (b << 10) | p;
        float zv = z[i];
        float q  = cb[g_idx[n] * DIM + d];
        float diff = __fsub_rn(q, zv);
        out[i] = __fadd_rn(zv, diff);
        local = __fmaf_rn(diff, diff, local);
    }
    __shared__ float s[8];
    #pragma unroll
    for (int o = 16; o; o >>= 1) local += __shfl_down_sync(0xffffffffu, local, o);
    if ((threadIdx.x & 31) == 0) s[threadIdx.x >> 5] = local;
    __syncthreads();
    if (threadIdx.x < 8) {
        float t = s[threadIdx.x];
        #pragma unroll
        for (int o = 4; o; o >>= 1) t += __shfl_down_sync(0xffu, t, o);
        if (threadIdx.x == 0) {
            atomicAdd(&g_loss, (double)t);
            __threadfence();
            unsigned r = atomicAdd(&g_done, 1u);
            if (r == GL_BLOCKS - 1) {                 // last block: finalize
                double total = atomicAdd(&g_loss, 0.0);
                if (write_loss) out[LOSS_OFF] = (float)(1.25 * total / (double)ZQ_ELEMS);
                g_done = 0;                            // reset for next graph replay
            }
        }
    }
}

extern "C" void kernel_launch(void* const* d_in, const int* in_sizes, int n_in,
                              void* d_out, int out_size) {
    const float* z  = (const float*)d_in[0];
    const float* cb = (const float*)d_in[1];
    float* out = (float*)d_out;

    cudaFuncSetAttribute(gemm_hmma_k, cudaFuncAttributeMaxDynamicSharedMemorySize, HM_SMEM);

    int write_idx  = (out_size >= IDX_OFF + NPTS);
    int write_loss = (out_size >= LOSS_OFF + 1);

    norms_k<<<KCODE, 256>>>(cb);
    transpose_k<<<dim3(HW / 32, DIM / 32, BATCH), dim3(32, 8)>>>(z);
    rownorm_z_k<<<BATCH * 4, 256>>>(z);
    gemm_hmma_k<<<NPTS / 64, 128, HM_SMEM>>>();
    rescore_k<<<NPTS / 8, 256>>>(cb, out, write_idx);
    gather_loss_k<<<GL_BLOCKS, 256>>>(z, cb, out, write_loss);
}